// round 12
// baseline (speedup 1.0000x reference)
#include <cuda_runtime.h>
#include <math.h>

#define TT 512
typedef unsigned long long ull;

// ---------------- static device scratch (no allocation allowed) --------------
__device__ float g_WxE[512 * 4096];               // permuted enc_W x-part  (E=512)
__device__ float g_WhE[1024 * 4096];              // permuted enc_W h-part  (H=1024)
__device__ float g_WhD[1024 * 4096];              // permuted dec_W h-part
__device__ float g_WxD[64 * 4096];                // permuted dec_W x-part (+ dec_b folded)
__device__ float g_bE[4096];                      // permuted enc_b
__device__ float g_Xe[(size_t)512 * 64 * 4096];   // encoder x-projections (+ enc_b folded)
__device__ float g_h[2][64 * 1024];               // encoder h ping-pong
__device__ float g_c[64 * 1024];                  // cell state (in place)
__device__ float g_Hdec[(size_t)512 * 64 * 1024]; // decoder hidden states
__device__ ull   g_bar;                           // monotonic grid-barrier ticket

// ---------------- helpers ----------------------------------------------------
__device__ __forceinline__ void ffma2(ull& d, ull a, ull b) {
    asm("fma.rn.f32x2 %0, %1, %2, %0;" : "+l"(d) : "l"(a), "l"(b));
}
__device__ __forceinline__ ull dup2(float x) {
    ull r; asm("mov.b64 %0, {%1,%1};" : "=l"(r) : "f"(x)); return r;
}
__device__ __forceinline__ float2 upk2(ull v) {
    float2 r; asm("mov.b64 {%0,%1}, %2;" : "=f"(r.x), "=f"(r.y) : "l"(v)); return r;
}
__device__ __forceinline__ float sigf(float x) { return 1.0f / (1.0f + expf(-x)); }

// Replay-safe grid barrier: every launch increments g_bar by (#steps * 128),
// a multiple of 128, so ticket%128 is always this phase's rank.
__device__ __forceinline__ void grid_bar() {
    __syncthreads();
    if (threadIdx.x == 0) {
        ull old;
        asm volatile("atom.release.gpu.global.add.u64 %0, [%1], %2;"
                     : "=l"(old) : "l"(&g_bar), "l"(1ull) : "memory");
        ull target = old - (old & 127ull) + 128ull;
        ull v;
        do {
            asm volatile("ld.acquire.gpu.global.u64 %0, [%1];"
                         : "=l"(v) : "l"(&g_bar) : "memory");
        } while (v < target);
    }
    __syncthreads();
}

// ---------------- prep: gate-interleave weights, zero state -------------------
// permuted col n' = j*4 + gate  <-  original col = gate*1024 + j
__global__ void __launch_bounds__(256) prep_k(
    const float* __restrict__ encW, const float* __restrict__ encB,
    const float* __restrict__ decW, const float* __restrict__ decB)
{
    int idx = blockIdx.x * 256 + threadIdx.x;
    if (idx < 1024 * 4096) {
        int k = idx >> 12, n = idx & 4095;
        int j = n >> 2, g = n & 3;
        int sc = g * 1024 + j;
        g_WhE[idx] = encW[(size_t)(512 + k) * 4096 + sc];
        g_WhD[idx] = decW[(size_t)(64 + k) * 4096 + sc];
        if (k < 512) g_WxE[(size_t)k * 4096 + n] = encW[(size_t)k * 4096 + sc];
        if (k < 64)  g_WxD[(size_t)k * 4096 + n] = decW[(size_t)k * 4096 + sc] + decB[sc];
        if (k == 0)  g_bE[n] = encB[sc];
    }
    if (idx < 65536) { g_h[0][idx] = 0.0f; g_c[idx] = 0.0f; }
}

// ---------------- phase A: Xe = emb[src] @ WxE + bE ---------------------------
// M=32768 (m = t*64+b), N=4096, K=512. CTA 128x128, KT=32, 256 thr,
// thread tile 8 rows (4 f32x2 row-pairs) x 8 cols. Register prefetch pipeline.
__global__ void __launch_bounds__(256) phaseA_k(const int* __restrict__ src,
                                                const float* __restrict__ emb)
{
    __shared__ __align__(16) float As[32][134];   // [k][row]
    __shared__ __align__(16) float Bs[32][132];   // [k][col]
    __shared__ int tok[128];

    const int tid = threadIdx.x;
    const int n0 = blockIdx.x * 128, m0 = blockIdx.y * 128;
    if (tid < 128) { int m = m0 + tid; tok[tid] = src[(m & 63) * TT + (m >> 6)]; }
    __syncthreads();

    const int rg = tid >> 4;   // rows rg*8..rg*8+7
    const int cg = tid & 15;   // cols cg*8..cg*8+7
    ull acc[4][8];
    #pragma unroll
    for (int p = 0; p < 4; p++)
        #pragma unroll
        for (int q = 0; q < 8; q++) acc[p][q] = 0ull;

    float4 gA[4], gB[4];
    #pragma unroll
    for (int i = 0; i < 4; i++) {
        int idx = tid + i * 256;
        int r = idx >> 3, f4 = idx & 7;
        gA[i] = *(const float4*)&emb[(size_t)tok[r] * 512 + f4 * 4];
        int kk = idx >> 5, c4 = idx & 31;
        gB[i] = *(const float4*)&g_WxE[(size_t)kk * 4096 + n0 + c4 * 4];
    }
    #pragma unroll
    for (int i = 0; i < 4; i++) {
        int idx = tid + i * 256;
        int r = idx >> 3, f4 = idx & 7;
        As[f4 * 4 + 0][r] = gA[i].x; As[f4 * 4 + 1][r] = gA[i].y;
        As[f4 * 4 + 2][r] = gA[i].z; As[f4 * 4 + 3][r] = gA[i].w;
        int kk = idx >> 5, c4 = idx & 31;
        *(float4*)&Bs[kk][c4 * 4] = gB[i];
    }
    __syncthreads();

    for (int k0 = 0; k0 < 512; k0 += 32) {
        const bool more = (k0 + 32) < 512;
        if (more) {
            #pragma unroll
            for (int i = 0; i < 4; i++) {
                int idx = tid + i * 256;
                int r = idx >> 3, f4 = idx & 7;
                gA[i] = *(const float4*)&emb[(size_t)tok[r] * 512 + k0 + 32 + f4 * 4];
                int kk = idx >> 5, c4 = idx & 31;
                gB[i] = *(const float4*)&g_WxE[(size_t)(k0 + 32 + kk) * 4096 + n0 + c4 * 4];
            }
        }
        #pragma unroll
        for (int k = 0; k < 32; k++) {
            ull a[4];
            #pragma unroll
            for (int p = 0; p < 4; p++) a[p] = *(const ull*)&As[k][rg * 8 + 2 * p];
            float4 w0 = *(const float4*)&Bs[k][cg * 8];
            float4 w1 = *(const float4*)&Bs[k][cg * 8 + 4];
            ull b[8] = { dup2(w0.x), dup2(w0.y), dup2(w0.z), dup2(w0.w),
                         dup2(w1.x), dup2(w1.y), dup2(w1.z), dup2(w1.w) };
            #pragma unroll
            for (int p = 0; p < 4; p++)
                #pragma unroll
                for (int q = 0; q < 8; q++) ffma2(acc[p][q], a[p], b[q]);
        }
        __syncthreads();
        if (more) {
            #pragma unroll
            for (int i = 0; i < 4; i++) {
                int idx = tid + i * 256;
                int r = idx >> 3, f4 = idx & 7;
                As[f4 * 4 + 0][r] = gA[i].x; As[f4 * 4 + 1][r] = gA[i].y;
                As[f4 * 4 + 2][r] = gA[i].z; As[f4 * 4 + 3][r] = gA[i].w;
                int kk = idx >> 5, c4 = idx & 31;
                *(float4*)&Bs[kk][c4 * 4] = gB[i];
            }
            __syncthreads();
        }
    }

    float4 b0 = *(const float4*)&g_bE[n0 + cg * 8];
    float4 b1 = *(const float4*)&g_bE[n0 + cg * 8 + 4];
    #pragma unroll
    for (int p = 0; p < 4; p++) {
        float lo[8], hi[8];
        #pragma unroll
        for (int q = 0; q < 8; q++) { float2 v = upk2(acc[p][q]); lo[q] = v.x; hi[q] = v.y; }
        size_t r0 = (size_t)(m0 + rg * 8 + 2 * p);
        float* o0 = &g_Xe[r0 * 4096 + n0 + cg * 8];
        float* o1 = o0 + 4096;
        *(float4*)(o0)     = make_float4(lo[0] + b0.x, lo[1] + b0.y, lo[2] + b0.z, lo[3] + b0.w);
        *(float4*)(o0 + 4) = make_float4(lo[4] + b1.x, lo[5] + b1.y, lo[6] + b1.z, lo[7] + b1.w);
        *(float4*)(o1)     = make_float4(hi[0] + b0.x, hi[1] + b0.y, hi[2] + b0.z, hi[3] + b0.w);
        *(float4*)(o1 + 4) = make_float4(hi[4] + b1.x, hi[5] + b1.y, hi[6] + b1.z, hi[7] + b1.w);
    }
}

// ---------------- persistent LSTM recurrence (512 steps in one kernel) --------
// 128 CTAs x 256 thr; CTA owns 32 permuted cols (8 hidden units).
// Wh slice (1024x32, 128KB) cached in SMEM for the whole kernel.
// 8-way K-split: warp w handles k in [w*128, w*128+128) and computes the FULL
// 64x32 output tile over its slice. Thread tile 8 rows x 8 cols; f32x2 packs
// natural row pairs (h staged transposed A[k][batch], no duplication).
// Partials reduced through SMEM (reusing the A-tile region), cell update
// distributed across all 256 threads.
// SMEM floats: Wh_s[32768] | At[8 warps][2 bufs][16k][68] = 17408 (alias red[8][2048]) | tok[64]
#define SMEM_PERSIST 200960

template <bool DEC>
__global__ void __launch_bounds__(256, 1) persist_k(const int* __restrict__ trg)
{
    extern __shared__ float smem[];
    float* Wh_s = smem;                         // [1024*32]
    float* At   = smem + 32768;                 // [8][2][1088]
    float* red  = At;                           // alias: [8][2048]
    int*   tok  = (int*)(smem + 32768 + 17408); // [64]

    const int tid  = threadIdx.x;
    const int n0   = blockIdx.x * 32;
    const int w    = tid >> 5;
    const int lane = tid & 31;
    const int rg   = lane >> 2;     // rows rg*8 .. rg*8+7
    const int cl   = lane & 3;      // cols cl*8 .. cl*8+7
    const int kwarp = w * 128;
    const float* __restrict__ Whg = DEC ? g_WhD : g_WhE;

    // one-time: load this CTA's Wh slice into SMEM (8192 float4)
    for (int i = 0; i < 32; i++) {
        int e = (tid + i * 256) * 4;
        int k = e >> 5, c = e & 31;
        *(float4*)&Wh_s[e] = *(const float4*)&Whg[(size_t)k * 4096 + n0 + c];
    }
    __syncthreads();

    float* At0 = At + w * 2176;     // this warp's double buffer (2 x 1088 floats)

    for (int t = 0; t < 512; t++) {
        const float* __restrict__ h_in;
        float* __restrict__ h_out;
        if (DEC) {
            h_in  = (t == 0) ? g_h[0] : &g_Hdec[(size_t)(t - 1) * 65536];
            h_out = &g_Hdec[(size_t)t * 65536];
            if (tid < 64) tok[tid] = trg[tid * TT + t];
        } else {
            h_in  = g_h[t & 1];
            h_out = g_h[(t + 1) & 1];
        }

        ull acc[4][8];
        #pragma unroll
        for (int p = 0; p < 4; p++)
            #pragma unroll
            for (int q = 0; q < 8; q++) acc[p][q] = 0ull;

        // stage tile 0 (transpose h -> A[k][batch], stride 68)
        float4 pf[8];
        #pragma unroll
        for (int i = 0; i < 8; i++) {
            int idx = i * 32 + lane;
            int b = idx >> 2, kq = idx & 3;
            pf[i] = *(const float4*)&h_in[b * 1024 + kwarp + kq * 4];
        }
        #pragma unroll
        for (int i = 0; i < 8; i++) {
            int idx = i * 32 + lane;
            int b = idx >> 2, kq = idx & 3;
            float* d = At0 + (kq * 4) * 68 + b;
            d[0] = pf[i].x; d[68] = pf[i].y; d[136] = pf[i].z; d[204] = pf[i].w;
        }
        __syncwarp();

        for (int tt = 0; tt < 8; tt++) {
            if (tt < 7) {
                #pragma unroll
                for (int i = 0; i < 8; i++) {
                    int idx = i * 32 + lane;
                    int b = idx >> 2, kq = idx & 3;
                    pf[i] = *(const float4*)&h_in[b * 1024 + kwarp + (tt + 1) * 16 + kq * 4];
                }
            }
            const float* Ab = At0 + (tt & 1) * 1088;
            const float* Wb = Wh_s + (kwarp + tt * 16) * 32;
            #pragma unroll
            for (int k = 0; k < 16; k++) {
                const float* Ak = Ab + k * 68 + rg * 8;
                ulonglong2 a01 = *(const ulonglong2*)(Ak);
                ulonglong2 a23 = *(const ulonglong2*)(Ak + 4);
                float4 w0 = *(const float4*)(Wb + k * 32 + cl * 8);
                float4 w1 = *(const float4*)(Wb + k * 32 + cl * 8 + 4);
                ull b0 = dup2(w0.x), b1 = dup2(w0.y), b2 = dup2(w0.z), b3 = dup2(w0.w);
                ull b4 = dup2(w1.x), b5 = dup2(w1.y), b6 = dup2(w1.z), b7 = dup2(w1.w);
                ffma2(acc[0][0], a01.x, b0); ffma2(acc[0][1], a01.x, b1);
                ffma2(acc[0][2], a01.x, b2); ffma2(acc[0][3], a01.x, b3);
                ffma2(acc[0][4], a01.x, b4); ffma2(acc[0][5], a01.x, b5);
                ffma2(acc[0][6], a01.x, b6); ffma2(acc[0][7], a01.x, b7);
                ffma2(acc[1][0], a01.y, b0); ffma2(acc[1][1], a01.y, b1);
                ffma2(acc[1][2], a01.y, b2); ffma2(acc[1][3], a01.y, b3);
                ffma2(acc[1][4], a01.y, b4); ffma2(acc[1][5], a01.y, b5);
                ffma2(acc[1][6], a01.y, b6); ffma2(acc[1][7], a01.y, b7);
                ffma2(acc[2][0], a23.x, b0); ffma2(acc[2][1], a23.x, b1);
                ffma2(acc[2][2], a23.x, b2); ffma2(acc[2][3], a23.x, b3);
                ffma2(acc[2][4], a23.x, b4); ffma2(acc[2][5], a23.x, b5);
                ffma2(acc[2][6], a23.x, b6); ffma2(acc[2][7], a23.x, b7);
                ffma2(acc[3][0], a23.y, b0); ffma2(acc[3][1], a23.y, b1);
                ffma2(acc[3][2], a23.y, b2); ffma2(acc[3][3], a23.y, b3);
                ffma2(acc[3][4], a23.y, b4); ffma2(acc[3][5], a23.y, b5);
                ffma2(acc[3][6], a23.y, b6); ffma2(acc[3][7], a23.y, b7);
            }
            if (tt < 7) {
                __syncwarp();
                float* d0 = At0 + ((tt & 1) ^ 1) * 1088;
                #pragma unroll
                for (int i = 0; i < 8; i++) {
                    int idx = i * 32 + lane;
                    int b = idx >> 2, kq = idx & 3;
                    float* d = d0 + (kq * 4) * 68 + b;
                    d[0] = pf[i].x; d[68] = pf[i].y; d[136] = pf[i].z; d[204] = pf[i].w;
                }
                __syncwarp();
            }
        }

        __syncthreads();
        // dump partials: red[w][col*64 + row] (col-major so row pairs stay packed)
        {
            float* rw = red + w * 2048;
            #pragma unroll
            for (int p = 0; p < 4; p++)
                #pragma unroll
                for (int q = 0; q < 8; q++)
                    *(ull*)&rw[(cl * 8 + q) * 64 + rg * 8 + 2 * p] = acc[p][q];
        }
        __syncthreads();

        // cell update: thread -> batch b = tid>>2, units (tid&3)*2 + {0,1}
        {
            int b = tid >> 2;
            #pragma unroll
            for (int jl = 0; jl < 2; jl++) {
                int j = (tid & 3) * 2 + jl;
                float s0 = 0.f, s1 = 0.f, s2 = 0.f, s3 = 0.f;
                #pragma unroll
                for (int ww = 0; ww < 8; ww++) {
                    const float* r = red + ww * 2048 + j * 256 + b;
                    s0 += r[0]; s1 += r[64]; s2 += r[128]; s3 += r[192];
                }
                float4 xq;
                if (DEC) xq = *(const float4*)&g_WxD[(size_t)tok[b] * 4096 + n0 + j * 4];
                else     xq = *(const float4*)&g_Xe[((size_t)t * 64 + b) * 4096 + n0 + j * 4];
                float gi = s0 + xq.x, gf = s1 + xq.y, gg = s2 + xq.z, go = s3 + xq.w;
                int ju = (n0 >> 2) + j;
                float co = g_c[b * 1024 + ju];
                float cn = sigf(gf) * co + sigf(gi) * tanhf(gg);
                g_c[b * 1024 + ju] = cn;
                h_out[b * 1024 + ju] = sigf(go) * tanhf(cn);
            }
        }
        grid_bar();
    }
}

// ---------------- phase C: logits = Hdec @ fc_W + fc_b ------------------------
__global__ void __launch_bounds__(256) phaseC_k(const float* __restrict__ fcW,
                                                const float* __restrict__ fcb,
                                                float* __restrict__ out)
{
    __shared__ __align__(16) float As[16][68];
    __shared__ __align__(16) float Bs[16][68];
    const int tid = threadIdx.x;
    const int m0 = blockIdx.x * 64;
    const int rg = tid >> 4, cg = tid & 15;
    float acc[4][4];
    #pragma unroll
    for (int p = 0; p < 4; p++)
        #pragma unroll
        for (int q = 0; q < 4; q++) acc[p][q] = 0.0f;

    for (int k0 = 0; k0 < 1024; k0 += 16) {
        { int r = tid >> 2, kq = tid & 3;
          float4 v = *(const float4*)&g_Hdec[(size_t)(m0 + r) * 1024 + k0 + kq * 4];
          As[kq * 4 + 0][r] = v.x; As[kq * 4 + 1][r] = v.y;
          As[kq * 4 + 2][r] = v.z; As[kq * 4 + 3][r] = v.w; }
        { int kk = tid >> 4, c4 = tid & 15;
          *(float4*)&Bs[kk][c4 * 4] = *(const float4*)&fcW[(size_t)(k0 + kk) * 64 + c4 * 4]; }
        __syncthreads();
        #pragma unroll
        for (int k = 0; k < 16; k++) {
            float4 a = *(const float4*)&As[k][rg * 4];
            float4 b = *(const float4*)&Bs[k][cg * 4];
            float av[4] = { a.x, a.y, a.z, a.w };
            float bv[4] = { b.x, b.y, b.z, b.w };
            #pragma unroll
            for (int p = 0; p < 4; p++)
                #pragma unroll
                for (int q = 0; q < 4; q++) acc[p][q] += av[p] * bv[q];
        }
        __syncthreads();
    }

    float4 bias = *(const float4*)&fcb[cg * 4];
    #pragma unroll
    for (int p = 0; p < 4; p++) {
        int m = m0 + rg * 4 + p;
        int b = m & 63, t = m >> 6;
        *(float4*)&out[(size_t)b * (512 * 64) + t * 64 + cg * 4] =
            make_float4(acc[p][0] + bias.x, acc[p][1] + bias.y,
                        acc[p][2] + bias.z, acc[p][3] + bias.w);
    }
}

// ---------------- launch ------------------------------------------------------
extern "C" void kernel_launch(void* const* d_in, const int* in_sizes, int n_in,
                              void* d_out, int out_size)
{
    const int*   src  = (const int*)d_in[0];
    const int*   trg  = (const int*)d_in[1];
    const float* emb  = (const float*)d_in[2];
    const float* encW = (const float*)d_in[3];
    const float* encB = (const float*)d_in[4];
    const float* decW = (const float*)d_in[5];
    const float* decB = (const float*)d_in[6];
    const float* fcW  = (const float*)d_in[7];
    const float* fcb  = (const float*)d_in[8];
    float* out = (float*)d_out;

    cudaFuncSetAttribute(persist_k<false>, cudaFuncAttributeMaxDynamicSharedMemorySize, SMEM_PERSIST);
    cudaFuncSetAttribute(persist_k<true>,  cudaFuncAttributeMaxDynamicSharedMemorySize, SMEM_PERSIST);

    prep_k<<<16384, 256>>>(encW, encB, decW, decB);
    phaseA_k<<<dim3(32, 256), 256>>>(src, emb);
    persist_k<false><<<128, 256, SMEM_PERSIST>>>((const int*)0);
    persist_k<true><<<128, 256, SMEM_PERSIST>>>(trg);
    phaseC_k<<<512, 256>>>(fcW, fcb, out);
}

// round 13
// speedup vs baseline: 1.0047x; 1.0047x over previous
#include <cuda_runtime.h>
#include <math.h>

#define TT 512
typedef unsigned long long ull;

// ---------------- static device scratch (no allocation allowed) --------------
__device__ float g_WxE[512 * 4096];               // permuted enc_W x-part  (E=512)
__device__ float g_WhE[1024 * 4096];              // permuted enc_W h-part  (H=1024)
__device__ float g_WhD[1024 * 4096];              // permuted dec_W h-part
__device__ float g_WxD[64 * 4096];                // permuted dec_W x-part (+ dec_b folded)
__device__ float g_bE[4096];                      // permuted enc_b
__device__ float g_Xe[(size_t)512 * 64 * 4096];   // encoder x-projections (+ enc_b folded)
__device__ float g_h[2][64 * 1024];               // encoder h ping-pong
__device__ float g_c[64 * 1024];                  // cell state (in place)
__device__ float g_Hdec[(size_t)512 * 64 * 1024]; // decoder hidden states
__device__ ull   g_bar;                           // monotonic grid-barrier ticket

// ---------------- helpers ----------------------------------------------------
__device__ __forceinline__ void ffma2(ull& d, ull a, ull b) {
    asm("fma.rn.f32x2 %0, %1, %2, %0;" : "+l"(d) : "l"(a), "l"(b));
}
__device__ __forceinline__ ull dup2(float x) {
    ull r; asm("mov.b64 %0, {%1,%1};" : "=l"(r) : "f"(x)); return r;
}
__device__ __forceinline__ float2 upk2(ull v) {
    float2 r; asm("mov.b64 {%0,%1}, %2;" : "=f"(r.x), "=f"(r.y) : "l"(v)); return r;
}
__device__ __forceinline__ float sigf(float x) { return 1.0f / (1.0f + expf(-x)); }

// Replay-safe grid barrier: every launch increments g_bar by (#steps * 128),
// a multiple of 128, so ticket%128 is always this phase's rank.
__device__ __forceinline__ void grid_bar() {
    __syncthreads();
    if (threadIdx.x == 0) {
        ull old;
        asm volatile("atom.release.gpu.global.add.u64 %0, [%1], %2;"
                     : "=l"(old) : "l"(&g_bar), "l"(1ull) : "memory");
        ull target = old - (old & 127ull) + 128ull;
        ull v;
        do {
            asm volatile("ld.acquire.gpu.global.u64 %0, [%1];"
                         : "=l"(v) : "l"(&g_bar) : "memory");
        } while (v < target);
    }
    __syncthreads();
}

// ---------------- prep: gate-interleave weights, zero state -------------------
// permuted col n' = j*4 + gate  <-  original col = gate*1024 + j
__global__ void __launch_bounds__(256) prep_k(
    const float* __restrict__ encW, const float* __restrict__ encB,
    const float* __restrict__ decW, const float* __restrict__ decB)
{
    int idx = blockIdx.x * 256 + threadIdx.x;
    if (idx < 1024 * 4096) {
        int k = idx >> 12, n = idx & 4095;
        int j = n >> 2, g = n & 3;
        int sc = g * 1024 + j;
        g_WhE[idx] = encW[(size_t)(512 + k) * 4096 + sc];
        g_WhD[idx] = decW[(size_t)(64 + k) * 4096 + sc];
        if (k < 512) g_WxE[(size_t)k * 4096 + n] = encW[(size_t)k * 4096 + sc];
        if (k < 64)  g_WxD[(size_t)k * 4096 + n] = decW[(size_t)k * 4096 + sc] + decB[sc];
        if (k == 0)  g_bE[n] = encB[sc];
    }
    if (idx < 65536) { g_h[0][idx] = 0.0f; g_c[idx] = 0.0f; }
}

// ---------------- phase A: Xe = emb[src] @ WxE + bE ---------------------------
// M=32768 (m = t*64+b), N=4096, K=512. CTA 128x128, KT=32, 256 thr,
// thread tile 8 rows (4 f32x2 row-pairs) x 8 cols. Register prefetch pipeline.
__global__ void __launch_bounds__(256) phaseA_k(const int* __restrict__ src,
                                                const float* __restrict__ emb)
{
    __shared__ __align__(16) float As[32][134];   // [k][row]
    __shared__ __align__(16) float Bs[32][132];   // [k][col]
    __shared__ int tok[128];

    const int tid = threadIdx.x;
    const int n0 = blockIdx.x * 128, m0 = blockIdx.y * 128;
    if (tid < 128) { int m = m0 + tid; tok[tid] = src[(m & 63) * TT + (m >> 6)]; }
    __syncthreads();

    const int rg = tid >> 4;   // rows rg*8..rg*8+7
    const int cg = tid & 15;   // cols cg*8..cg*8+7
    ull acc[4][8];
    #pragma unroll
    for (int p = 0; p < 4; p++)
        #pragma unroll
        for (int q = 0; q < 8; q++) acc[p][q] = 0ull;

    float4 gA[4], gB[4];
    #pragma unroll
    for (int i = 0; i < 4; i++) {
        int idx = tid + i * 256;
        int r = idx >> 3, f4 = idx & 7;
        gA[i] = *(const float4*)&emb[(size_t)tok[r] * 512 + f4 * 4];
        int kk = idx >> 5, c4 = idx & 31;
        gB[i] = *(const float4*)&g_WxE[(size_t)kk * 4096 + n0 + c4 * 4];
    }
    #pragma unroll
    for (int i = 0; i < 4; i++) {
        int idx = tid + i * 256;
        int r = idx >> 3, f4 = idx & 7;
        As[f4 * 4 + 0][r] = gA[i].x; As[f4 * 4 + 1][r] = gA[i].y;
        As[f4 * 4 + 2][r] = gA[i].z; As[f4 * 4 + 3][r] = gA[i].w;
        int kk = idx >> 5, c4 = idx & 31;
        *(float4*)&Bs[kk][c4 * 4] = gB[i];
    }
    __syncthreads();

    for (int k0 = 0; k0 < 512; k0 += 32) {
        const bool more = (k0 + 32) < 512;
        if (more) {
            #pragma unroll
            for (int i = 0; i < 4; i++) {
                int idx = tid + i * 256;
                int r = idx >> 3, f4 = idx & 7;
                gA[i] = *(const float4*)&emb[(size_t)tok[r] * 512 + k0 + 32 + f4 * 4];
                int kk = idx >> 5, c4 = idx & 31;
                gB[i] = *(const float4*)&g_WxE[(size_t)(k0 + 32 + kk) * 4096 + n0 + c4 * 4];
            }
        }
        #pragma unroll
        for (int k = 0; k < 32; k++) {
            ull a[4];
            #pragma unroll
            for (int p = 0; p < 4; p++) a[p] = *(const ull*)&As[k][rg * 8 + 2 * p];
            float4 w0 = *(const float4*)&Bs[k][cg * 8];
            float4 w1 = *(const float4*)&Bs[k][cg * 8 + 4];
            ull b[8] = { dup2(w0.x), dup2(w0.y), dup2(w0.z), dup2(w0.w),
                         dup2(w1.x), dup2(w1.y), dup2(w1.z), dup2(w1.w) };
            #pragma unroll
            for (int p = 0; p < 4; p++)
                #pragma unroll
                for (int q = 0; q < 8; q++) ffma2(acc[p][q], a[p], b[q]);
        }
        __syncthreads();
        if (more) {
            #pragma unroll
            for (int i = 0; i < 4; i++) {
                int idx = tid + i * 256;
                int r = idx >> 3, f4 = idx & 7;
                As[f4 * 4 + 0][r] = gA[i].x; As[f4 * 4 + 1][r] = gA[i].y;
                As[f4 * 4 + 2][r] = gA[i].z; As[f4 * 4 + 3][r] = gA[i].w;
                int kk = idx >> 5, c4 = idx & 31;
                *(float4*)&Bs[kk][c4 * 4] = gB[i];
            }
            __syncthreads();
        }
    }

    float4 b0 = *(const float4*)&g_bE[n0 + cg * 8];
    float4 b1 = *(const float4*)&g_bE[n0 + cg * 8 + 4];
    #pragma unroll
    for (int p = 0; p < 4; p++) {
        float lo[8], hi[8];
        #pragma unroll
        for (int q = 0; q < 8; q++) { float2 v = upk2(acc[p][q]); lo[q] = v.x; hi[q] = v.y; }
        size_t r0 = (size_t)(m0 + rg * 8 + 2 * p);
        float* o0 = &g_Xe[r0 * 4096 + n0 + cg * 8];
        float* o1 = o0 + 4096;
        *(float4*)(o0)     = make_float4(lo[0] + b0.x, lo[1] + b0.y, lo[2] + b0.z, lo[3] + b0.w);
        *(float4*)(o0 + 4) = make_float4(lo[4] + b1.x, lo[5] + b1.y, lo[6] + b1.z, lo[7] + b1.w);
        *(float4*)(o1)     = make_float4(hi[0] + b0.x, hi[1] + b0.y, hi[2] + b0.z, hi[3] + b0.w);
        *(float4*)(o1 + 4) = make_float4(hi[4] + b1.x, hi[5] + b1.y, hi[6] + b1.z, hi[7] + b1.w);
    }
}

// ---------------- persistent LSTM recurrence (512 steps in one kernel) --------
// 128 CTAs x 256 thr; CTA owns 32 permuted cols (8 hidden units).
// Wh slice (1024x32, 128KB) cached in SMEM for the whole kernel.
// 8-way K-split: warp w handles k in [w*128, w*128+128) and computes the FULL
// 64x32 output tile over its slice. Thread tile 8 rows x 8 cols; f32x2 packs
// natural row pairs (h staged transposed A[k][batch], no duplication).
// Partials reduced through SMEM (reusing the A-tile region), cell update
// distributed across all 256 threads.
// SMEM floats: Wh_s[32768] | At[8 warps][2 bufs][16k][68] = 17408 (alias red[8][2048]) | tok[64]
#define SMEM_PERSIST 200960

template <bool DEC>
__global__ void __launch_bounds__(256, 1) persist_k(const int* __restrict__ trg)
{
    extern __shared__ float smem[];
    float* Wh_s = smem;                         // [1024*32]
    float* At   = smem + 32768;                 // [8][2][1088]
    float* red  = At;                           // alias: [8][2048]
    int*   tok  = (int*)(smem + 32768 + 17408); // [64]

    const int tid  = threadIdx.x;
    const int n0   = blockIdx.x * 32;
    const int w    = tid >> 5;
    const int lane = tid & 31;
    const int rg   = lane >> 2;     // rows rg*8 .. rg*8+7
    const int cl   = lane & 3;      // cols cl*8 .. cl*8+7
    const int kwarp = w * 128;
    const float* __restrict__ Whg = DEC ? g_WhD : g_WhE;

    // one-time: load this CTA's Wh slice into SMEM (8192 float4)
    for (int i = 0; i < 32; i++) {
        int e = (tid + i * 256) * 4;
        int k = e >> 5, c = e & 31;
        *(float4*)&Wh_s[e] = *(const float4*)&Whg[(size_t)k * 4096 + n0 + c];
    }
    __syncthreads();

    float* At0 = At + w * 2176;     // this warp's double buffer (2 x 1088 floats)

    for (int t = 0; t < 512; t++) {
        const float* __restrict__ h_in;
        float* __restrict__ h_out;
        if (DEC) {
            h_in  = (t == 0) ? g_h[0] : &g_Hdec[(size_t)(t - 1) * 65536];
            h_out = &g_Hdec[(size_t)t * 65536];
            if (tid < 64) tok[tid] = trg[tid * TT + t];
        } else {
            h_in  = g_h[t & 1];
            h_out = g_h[(t + 1) & 1];
        }

        ull acc[4][8];
        #pragma unroll
        for (int p = 0; p < 4; p++)
            #pragma unroll
            for (int q = 0; q < 8; q++) acc[p][q] = 0ull;

        // stage tile 0 (transpose h -> A[k][batch], stride 68)
        float4 pf[8];
        #pragma unroll
        for (int i = 0; i < 8; i++) {
            int idx = i * 32 + lane;
            int b = idx >> 2, kq = idx & 3;
            pf[i] = *(const float4*)&h_in[b * 1024 + kwarp + kq * 4];
        }
        #pragma unroll
        for (int i = 0; i < 8; i++) {
            int idx = i * 32 + lane;
            int b = idx >> 2, kq = idx & 3;
            float* d = At0 + (kq * 4) * 68 + b;
            d[0] = pf[i].x; d[68] = pf[i].y; d[136] = pf[i].z; d[204] = pf[i].w;
        }
        __syncwarp();

        for (int tt = 0; tt < 8; tt++) {
            if (tt < 7) {
                #pragma unroll
                for (int i = 0; i < 8; i++) {
                    int idx = i * 32 + lane;
                    int b = idx >> 2, kq = idx & 3;
                    pf[i] = *(const float4*)&h_in[b * 1024 + kwarp + (tt + 1) * 16 + kq * 4];
                }
            }
            const float* Ab = At0 + (tt & 1) * 1088;
            const float* Wb = Wh_s + (kwarp + tt * 16) * 32;
            #pragma unroll
            for (int k = 0; k < 16; k++) {
                const float* Ak = Ab + k * 68 + rg * 8;
                ulonglong2 a01 = *(const ulonglong2*)(Ak);
                ulonglong2 a23 = *(const ulonglong2*)(Ak + 4);
                float4 w0 = *(const float4*)(Wb + k * 32 + cl * 8);
                float4 w1 = *(const float4*)(Wb + k * 32 + cl * 8 + 4);
                ull b0 = dup2(w0.x), b1 = dup2(w0.y), b2 = dup2(w0.z), b3 = dup2(w0.w);
                ull b4 = dup2(w1.x), b5 = dup2(w1.y), b6 = dup2(w1.z), b7 = dup2(w1.w);
                ffma2(acc[0][0], a01.x, b0); ffma2(acc[0][1], a01.x, b1);
                ffma2(acc[0][2], a01.x, b2); ffma2(acc[0][3], a01.x, b3);
                ffma2(acc[0][4], a01.x, b4); ffma2(acc[0][5], a01.x, b5);
                ffma2(acc[0][6], a01.x, b6); ffma2(acc[0][7], a01.x, b7);
                ffma2(acc[1][0], a01.y, b0); ffma2(acc[1][1], a01.y, b1);
                ffma2(acc[1][2], a01.y, b2); ffma2(acc[1][3], a01.y, b3);
                ffma2(acc[1][4], a01.y, b4); ffma2(acc[1][5], a01.y, b5);
                ffma2(acc[1][6], a01.y, b6); ffma2(acc[1][7], a01.y, b7);
                ffma2(acc[2][0], a23.x, b0); ffma2(acc[2][1], a23.x, b1);
                ffma2(acc[2][2], a23.x, b2); ffma2(acc[2][3], a23.x, b3);
                ffma2(acc[2][4], a23.x, b4); ffma2(acc[2][5], a23.x, b5);
                ffma2(acc[2][6], a23.x, b6); ffma2(acc[2][7], a23.x, b7);
                ffma2(acc[3][0], a23.y, b0); ffma2(acc[3][1], a23.y, b1);
                ffma2(acc[3][2], a23.y, b2); ffma2(acc[3][3], a23.y, b3);
                ffma2(acc[3][4], a23.y, b4); ffma2(acc[3][5], a23.y, b5);
                ffma2(acc[3][6], a23.y, b6); ffma2(acc[3][7], a23.y, b7);
            }
            if (tt < 7) {
                __syncwarp();
                float* d0 = At0 + ((tt & 1) ^ 1) * 1088;
                #pragma unroll
                for (int i = 0; i < 8; i++) {
                    int idx = i * 32 + lane;
                    int b = idx >> 2, kq = idx & 3;
                    float* d = d0 + (kq * 4) * 68 + b;
                    d[0] = pf[i].x; d[68] = pf[i].y; d[136] = pf[i].z; d[204] = pf[i].w;
                }
                __syncwarp();
            }
        }

        __syncthreads();
        // dump partials: red[w][col*64 + row] (col-major so row pairs stay packed)
        {
            float* rw = red + w * 2048;
            #pragma unroll
            for (int p = 0; p < 4; p++)
                #pragma unroll
                for (int q = 0; q < 8; q++)
                    *(ull*)&rw[(cl * 8 + q) * 64 + rg * 8 + 2 * p] = acc[p][q];
        }
        __syncthreads();

        // cell update: thread -> batch b = tid>>2, units (tid&3)*2 + {0,1}
        {
            int b = tid >> 2;
            #pragma unroll
            for (int jl = 0; jl < 2; jl++) {
                int j = (tid & 3) * 2 + jl;
                float s0 = 0.f, s1 = 0.f, s2 = 0.f, s3 = 0.f;
                #pragma unroll
                for (int ww = 0; ww < 8; ww++) {
                    const float* r = red + ww * 2048 + j * 256 + b;
                    s0 += r[0]; s1 += r[64]; s2 += r[128]; s3 += r[192];
                }
                float4 xq;
                if (DEC) xq = *(const float4*)&g_WxD[(size_t)tok[b] * 4096 + n0 + j * 4];
                else     xq = *(const float4*)&g_Xe[((size_t)t * 64 + b) * 4096 + n0 + j * 4];
                float gi = s0 + xq.x, gf = s1 + xq.y, gg = s2 + xq.z, go = s3 + xq.w;
                int ju = (n0 >> 2) + j;
                float co = g_c[b * 1024 + ju];
                float cn = sigf(gf) * co + sigf(gi) * tanhf(gg);
                g_c[b * 1024 + ju] = cn;
                h_out[b * 1024 + ju] = sigf(go) * tanhf(cn);
            }
        }
        grid_bar();
    }
}

// ---------------- phase C: logits = Hdec @ fc_W + fc_b ------------------------
__global__ void __launch_bounds__(256) phaseC_k(const float* __restrict__ fcW,
                                                const float* __restrict__ fcb,
                                                float* __restrict__ out)
{
    __shared__ __align__(16) float As[16][68];
    __shared__ __align__(16) float Bs[16][68];
    const int tid = threadIdx.x;
    const int m0 = blockIdx.x * 64;
    const int rg = tid >> 4, cg = tid & 15;
    float acc[4][4];
    #pragma unroll
    for (int p = 0; p < 4; p++)
        #pragma unroll
        for (int q = 0; q < 4; q++) acc[p][q] = 0.0f;

    for (int k0 = 0; k0 < 1024; k0 += 16) {
        { int r = tid >> 2, kq = tid & 3;
          float4 v = *(const float4*)&g_Hdec[(size_t)(m0 + r) * 1024 + k0 + kq * 4];
          As[kq * 4 + 0][r] = v.x; As[kq * 4 + 1][r] = v.y;
          As[kq * 4 + 2][r] = v.z; As[kq * 4 + 3][r] = v.w; }
        { int kk = tid >> 4, c4 = tid & 15;
          *(float4*)&Bs[kk][c4 * 4] = *(const float4*)&fcW[(size_t)(k0 + kk) * 64 + c4 * 4]; }
        __syncthreads();
        #pragma unroll
        for (int k = 0; k < 16; k++) {
            float4 a = *(const float4*)&As[k][rg * 4];
            float4 b = *(const float4*)&Bs[k][cg * 4];
            float av[4] = { a.x, a.y, a.z, a.w };
            float bv[4] = { b.x, b.y, b.z, b.w };
            #pragma unroll
            for (int p = 0; p < 4; p++)
                #pragma unroll
                for (int q = 0; q < 4; q++) acc[p][q] += av[p] * bv[q];
        }
        __syncthreads();
    }

    float4 bias = *(const float4*)&fcb[cg * 4];
    #pragma unroll
    for (int p = 0; p < 4; p++) {
        int m = m0 + rg * 4 + p;
        int b = m & 63, t = m >> 6;
        *(float4*)&out[(size_t)b * (512 * 64) + t * 64 + cg * 4] =
            make_float4(acc[p][0] + bias.x, acc[p][1] + bias.y,
                        acc[p][2] + bias.z, acc[p][3] + bias.w);
    }
}

// ---------------- launch ------------------------------------------------------
extern "C" void kernel_launch(void* const* d_in, const int* in_sizes, int n_in,
                              void* d_out, int out_size)
{
    const int*   src  = (const int*)d_in[0];
    const int*   trg  = (const int*)d_in[1];
    const float* emb  = (const float*)d_in[2];
    const float* encW = (const float*)d_in[3];
    const float* encB = (const float*)d_in[4];
    const float* decW = (const float*)d_in[5];
    const float* decB = (const float*)d_in[6];
    const float* fcW  = (const float*)d_in[7];
    const float* fcb  = (const float*)d_in[8];
    float* out = (float*)d_out;

    cudaFuncSetAttribute(persist_k<false>, cudaFuncAttributeMaxDynamicSharedMemorySize, SMEM_PERSIST);
    cudaFuncSetAttribute(persist_k<true>,  cudaFuncAttributeMaxDynamicSharedMemorySize, SMEM_PERSIST);

    prep_k<<<16384, 256>>>(encW, encB, decW, decB);
    phaseA_k<<<dim3(32, 256), 256>>>(src, emb);
    persist_k<false><<<128, 256, SMEM_PERSIST>>>((const int*)0);
    persist_k<true><<<128, 256, SMEM_PERSIST>>>(trg);
    phaseC_k<<<512, 256>>>(fcW, fcb, out);
}

// round 14
// speedup vs baseline: 1.0063x; 1.0016x over previous
#include <cuda_runtime.h>
#include <math.h>

#define TT 512
typedef unsigned long long ull;

// ---------------- static device scratch (no allocation allowed) --------------
__device__ float g_WxE[512 * 4096];               // permuted enc_W x-part  (E=512)
__device__ float g_WhE[1024 * 4096];              // permuted enc_W h-part  (H=1024)
__device__ float g_WhD[1024 * 4096];              // permuted dec_W h-part
__device__ float g_WxD[64 * 4096];                // permuted dec_W x-part (+ dec_b folded)
__device__ float g_bE[4096];                      // permuted enc_b
__device__ float g_Xe[(size_t)512 * 64 * 4096];   // encoder x-projections (+ enc_b folded)
__device__ float g_h[2][64 * 1024];               // encoder h ping-pong
__device__ float g_c[64 * 1024];                  // cell state (in place)
__device__ float g_Hdec[(size_t)512 * 64 * 1024]; // decoder hidden states
__device__ ull   g_bar;                           // monotonic grid-barrier ticket

// ---------------- helpers ----------------------------------------------------
__device__ __forceinline__ void ffma2(ull& d, ull a, ull b) {
    asm("fma.rn.f32x2 %0, %1, %2, %0;" : "+l"(d) : "l"(a), "l"(b));
}
__device__ __forceinline__ ull dup2(float x) {
    ull r; asm("mov.b64 %0, {%1,%1};" : "=l"(r) : "f"(x)); return r;
}
__device__ __forceinline__ float2 upk2(ull v) {
    float2 r; asm("mov.b64 {%0,%1}, %2;" : "=f"(r.x), "=f"(r.y) : "l"(v)); return r;
}
__device__ __forceinline__ float sigf(float x) { return 1.0f / (1.0f + expf(-x)); }

// Replay-safe grid barrier: every launch increments g_bar by (#steps * 128),
// a multiple of 128, so ticket%128 is always this phase's rank.
__device__ __forceinline__ void grid_bar() {
    __syncthreads();
    if (threadIdx.x == 0) {
        ull old;
        asm volatile("atom.release.gpu.global.add.u64 %0, [%1], %2;"
                     : "=l"(old) : "l"(&g_bar), "l"(1ull) : "memory");
        ull target = old - (old & 127ull) + 128ull;
        ull v;
        do {
            asm volatile("ld.acquire.gpu.global.u64 %0, [%1];"
                         : "=l"(v) : "l"(&g_bar) : "memory");
        } while (v < target);
    }
    __syncthreads();
}

// ---------------- prep: gate-interleave weights, zero state -------------------
// permuted col n' = j*4 + gate  <-  original col = gate*1024 + j
__global__ void __launch_bounds__(256) prep_k(
    const float* __restrict__ encW, const float* __restrict__ encB,
    const float* __restrict__ decW, const float* __restrict__ decB)
{
    int idx = blockIdx.x * 256 + threadIdx.x;
    if (idx < 1024 * 4096) {
        int k = idx >> 12, n = idx & 4095;
        int j = n >> 2, g = n & 3;
        int sc = g * 1024 + j;
        g_WhE[idx] = encW[(size_t)(512 + k) * 4096 + sc];
        g_WhD[idx] = decW[(size_t)(64 + k) * 4096 + sc];
        if (k < 512) g_WxE[(size_t)k * 4096 + n] = encW[(size_t)k * 4096 + sc];
        if (k < 64)  g_WxD[(size_t)k * 4096 + n] = decW[(size_t)k * 4096 + sc] + decB[sc];
        if (k == 0)  g_bE[n] = encB[sc];
    }
    if (idx < 65536) { g_h[0][idx] = 0.0f; g_c[idx] = 0.0f; }
}

// ---------------- phase A: Xe = emb[src] @ WxE + bE ---------------------------
// M=32768 (m = t*64+b), N=4096, K=512. CTA 128x128, KT=32, 256 thr,
// thread tile 8 rows (4 f32x2 row-pairs) x 8 cols. Register prefetch pipeline.
__global__ void __launch_bounds__(256) phaseA_k(const int* __restrict__ src,
                                                const float* __restrict__ emb)
{
    __shared__ __align__(16) float As[32][134];   // [k][row]
    __shared__ __align__(16) float Bs[32][132];   // [k][col]
    __shared__ int tok[128];

    const int tid = threadIdx.x;
    const int n0 = blockIdx.x * 128, m0 = blockIdx.y * 128;
    if (tid < 128) { int m = m0 + tid; tok[tid] = src[(m & 63) * TT + (m >> 6)]; }
    __syncthreads();

    const int rg = tid >> 4;   // rows rg*8..rg*8+7
    const int cg = tid & 15;   // cols cg*8..cg*8+7
    ull acc[4][8];
    #pragma unroll
    for (int p = 0; p < 4; p++)
        #pragma unroll
        for (int q = 0; q < 8; q++) acc[p][q] = 0ull;

    float4 gA[4], gB[4];
    #pragma unroll
    for (int i = 0; i < 4; i++) {
        int idx = tid + i * 256;
        int r = idx >> 3, f4 = idx & 7;
        gA[i] = *(const float4*)&emb[(size_t)tok[r] * 512 + f4 * 4];
        int kk = idx >> 5, c4 = idx & 31;
        gB[i] = *(const float4*)&g_WxE[(size_t)kk * 4096 + n0 + c4 * 4];
    }
    #pragma unroll
    for (int i = 0; i < 4; i++) {
        int idx = tid + i * 256;
        int r = idx >> 3, f4 = idx & 7;
        As[f4 * 4 + 0][r] = gA[i].x; As[f4 * 4 + 1][r] = gA[i].y;
        As[f4 * 4 + 2][r] = gA[i].z; As[f4 * 4 + 3][r] = gA[i].w;
        int kk = idx >> 5, c4 = idx & 31;
        *(float4*)&Bs[kk][c4 * 4] = gB[i];
    }
    __syncthreads();

    for (int k0 = 0; k0 < 512; k0 += 32) {
        const bool more = (k0 + 32) < 512;
        if (more) {
            #pragma unroll
            for (int i = 0; i < 4; i++) {
                int idx = tid + i * 256;
                int r = idx >> 3, f4 = idx & 7;
                gA[i] = *(const float4*)&emb[(size_t)tok[r] * 512 + k0 + 32 + f4 * 4];
                int kk = idx >> 5, c4 = idx & 31;
                gB[i] = *(const float4*)&g_WxE[(size_t)(k0 + 32 + kk) * 4096 + n0 + c4 * 4];
            }
        }
        #pragma unroll
        for (int k = 0; k < 32; k++) {
            ull a[4];
            #pragma unroll
            for (int p = 0; p < 4; p++) a[p] = *(const ull*)&As[k][rg * 8 + 2 * p];
            float4 w0 = *(const float4*)&Bs[k][cg * 8];
            float4 w1 = *(const float4*)&Bs[k][cg * 8 + 4];
            ull b[8] = { dup2(w0.x), dup2(w0.y), dup2(w0.z), dup2(w0.w),
                         dup2(w1.x), dup2(w1.y), dup2(w1.z), dup2(w1.w) };
            #pragma unroll
            for (int p = 0; p < 4; p++)
                #pragma unroll
                for (int q = 0; q < 8; q++) ffma2(acc[p][q], a[p], b[q]);
        }
        __syncthreads();
        if (more) {
            #pragma unroll
            for (int i = 0; i < 4; i++) {
                int idx = tid + i * 256;
                int r = idx >> 3, f4 = idx & 7;
                As[f4 * 4 + 0][r] = gA[i].x; As[f4 * 4 + 1][r] = gA[i].y;
                As[f4 * 4 + 2][r] = gA[i].z; As[f4 * 4 + 3][r] = gA[i].w;
                int kk = idx >> 5, c4 = idx & 31;
                *(float4*)&Bs[kk][c4 * 4] = gB[i];
            }
            __syncthreads();
        }
    }

    float4 b0 = *(const float4*)&g_bE[n0 + cg * 8];
    float4 b1 = *(const float4*)&g_bE[n0 + cg * 8 + 4];
    #pragma unroll
    for (int p = 0; p < 4; p++) {
        float lo[8], hi[8];
        #pragma unroll
        for (int q = 0; q < 8; q++) { float2 v = upk2(acc[p][q]); lo[q] = v.x; hi[q] = v.y; }
        size_t r0 = (size_t)(m0 + rg * 8 + 2 * p);
        float* o0 = &g_Xe[r0 * 4096 + n0 + cg * 8];
        float* o1 = o0 + 4096;
        *(float4*)(o0)     = make_float4(lo[0] + b0.x, lo[1] + b0.y, lo[2] + b0.z, lo[3] + b0.w);
        *(float4*)(o0 + 4) = make_float4(lo[4] + b1.x, lo[5] + b1.y, lo[6] + b1.z, lo[7] + b1.w);
        *(float4*)(o1)     = make_float4(hi[0] + b0.x, hi[1] + b0.y, hi[2] + b0.z, hi[3] + b0.w);
        *(float4*)(o1 + 4) = make_float4(hi[4] + b1.x, hi[5] + b1.y, hi[6] + b1.z, hi[7] + b1.w);
    }
}

// ---------------- persistent LSTM recurrence (512 steps in one kernel) --------
// 128 CTAs x 256 thr; CTA owns 32 permuted cols (8 hidden units).
// Wh slice (1024x32, 128KB) cached in SMEM for the whole kernel.
// 8-way K-split: warp w handles k in [w*128, w*128+128) and computes the FULL
// 64x32 output tile over its slice. Thread tile 8 rows x 8 cols; f32x2 packs
// natural row pairs (h staged transposed A[k][batch], no duplication).
// Partials reduced through SMEM (reusing the A-tile region), cell update
// distributed across all 256 threads.
// SMEM floats: Wh_s[32768] | At[8 warps][2 bufs][16k][68] = 17408 (alias red[8][2048]) | tok[64]
#define SMEM_PERSIST 200960

template <bool DEC>
__global__ void __launch_bounds__(256, 1) persist_k(const int* __restrict__ trg)
{
    extern __shared__ float smem[];
    float* Wh_s = smem;                         // [1024*32]
    float* At   = smem + 32768;                 // [8][2][1088]
    float* red  = At;                           // alias: [8][2048]
    int*   tok  = (int*)(smem + 32768 + 17408); // [64]

    const int tid  = threadIdx.x;
    const int n0   = blockIdx.x * 32;
    const int w    = tid >> 5;
    const int lane = tid & 31;
    const int rg   = lane >> 2;     // rows rg*8 .. rg*8+7
    const int cl   = lane & 3;      // cols cl*8 .. cl*8+7
    const int kwarp = w * 128;
    const float* __restrict__ Whg = DEC ? g_WhD : g_WhE;

    // one-time: load this CTA's Wh slice into SMEM (8192 float4)
    for (int i = 0; i < 32; i++) {
        int e = (tid + i * 256) * 4;
        int k = e >> 5, c = e & 31;
        *(float4*)&Wh_s[e] = *(const float4*)&Whg[(size_t)k * 4096 + n0 + c];
    }
    __syncthreads();

    float* At0 = At + w * 2176;     // this warp's double buffer (2 x 1088 floats)

    for (int t = 0; t < 512; t++) {
        const float* __restrict__ h_in;
        float* __restrict__ h_out;
        if (DEC) {
            h_in  = (t == 0) ? g_h[0] : &g_Hdec[(size_t)(t - 1) * 65536];
            h_out = &g_Hdec[(size_t)t * 65536];
            if (tid < 64) tok[tid] = trg[tid * TT + t];
        } else {
            h_in  = g_h[t & 1];
            h_out = g_h[(t + 1) & 1];
        }

        ull acc[4][8];
        #pragma unroll
        for (int p = 0; p < 4; p++)
            #pragma unroll
            for (int q = 0; q < 8; q++) acc[p][q] = 0ull;

        // stage tile 0 (transpose h -> A[k][batch], stride 68)
        float4 pf[8];
        #pragma unroll
        for (int i = 0; i < 8; i++) {
            int idx = i * 32 + lane;
            int b = idx >> 2, kq = idx & 3;
            pf[i] = *(const float4*)&h_in[b * 1024 + kwarp + kq * 4];
        }
        #pragma unroll
        for (int i = 0; i < 8; i++) {
            int idx = i * 32 + lane;
            int b = idx >> 2, kq = idx & 3;
            float* d = At0 + (kq * 4) * 68 + b;
            d[0] = pf[i].x; d[68] = pf[i].y; d[136] = pf[i].z; d[204] = pf[i].w;
        }
        __syncwarp();

        for (int tt = 0; tt < 8; tt++) {
            if (tt < 7) {
                #pragma unroll
                for (int i = 0; i < 8; i++) {
                    int idx = i * 32 + lane;
                    int b = idx >> 2, kq = idx & 3;
                    pf[i] = *(const float4*)&h_in[b * 1024 + kwarp + (tt + 1) * 16 + kq * 4];
                }
            }
            const float* Ab = At0 + (tt & 1) * 1088;
            const float* Wb = Wh_s + (kwarp + tt * 16) * 32;
            #pragma unroll
            for (int k = 0; k < 16; k++) {
                const float* Ak = Ab + k * 68 + rg * 8;
                ulonglong2 a01 = *(const ulonglong2*)(Ak);
                ulonglong2 a23 = *(const ulonglong2*)(Ak + 4);
                float4 w0 = *(const float4*)(Wb + k * 32 + cl * 8);
                float4 w1 = *(const float4*)(Wb + k * 32 + cl * 8 + 4);
                ull b0 = dup2(w0.x), b1 = dup2(w0.y), b2 = dup2(w0.z), b3 = dup2(w0.w);
                ull b4 = dup2(w1.x), b5 = dup2(w1.y), b6 = dup2(w1.z), b7 = dup2(w1.w);
                ffma2(acc[0][0], a01.x, b0); ffma2(acc[0][1], a01.x, b1);
                ffma2(acc[0][2], a01.x, b2); ffma2(acc[0][3], a01.x, b3);
                ffma2(acc[0][4], a01.x, b4); ffma2(acc[0][5], a01.x, b5);
                ffma2(acc[0][6], a01.x, b6); ffma2(acc[0][7], a01.x, b7);
                ffma2(acc[1][0], a01.y, b0); ffma2(acc[1][1], a01.y, b1);
                ffma2(acc[1][2], a01.y, b2); ffma2(acc[1][3], a01.y, b3);
                ffma2(acc[1][4], a01.y, b4); ffma2(acc[1][5], a01.y, b5);
                ffma2(acc[1][6], a01.y, b6); ffma2(acc[1][7], a01.y, b7);
                ffma2(acc[2][0], a23.x, b0); ffma2(acc[2][1], a23.x, b1);
                ffma2(acc[2][2], a23.x, b2); ffma2(acc[2][3], a23.x, b3);
                ffma2(acc[2][4], a23.x, b4); ffma2(acc[2][5], a23.x, b5);
                ffma2(acc[2][6], a23.x, b6); ffma2(acc[2][7], a23.x, b7);
                ffma2(acc[3][0], a23.y, b0); ffma2(acc[3][1], a23.y, b1);
                ffma2(acc[3][2], a23.y, b2); ffma2(acc[3][3], a23.y, b3);
                ffma2(acc[3][4], a23.y, b4); ffma2(acc[3][5], a23.y, b5);
                ffma2(acc[3][6], a23.y, b6); ffma2(acc[3][7], a23.y, b7);
            }
            if (tt < 7) {
                __syncwarp();
                float* d0 = At0 + ((tt & 1) ^ 1) * 1088;
                #pragma unroll
                for (int i = 0; i < 8; i++) {
                    int idx = i * 32 + lane;
                    int b = idx >> 2, kq = idx & 3;
                    float* d = d0 + (kq * 4) * 68 + b;
                    d[0] = pf[i].x; d[68] = pf[i].y; d[136] = pf[i].z; d[204] = pf[i].w;
                }
                __syncwarp();
            }
        }

        __syncthreads();
        // dump partials: red[w][col*64 + row] (col-major so row pairs stay packed)
        {
            float* rw = red + w * 2048;
            #pragma unroll
            for (int p = 0; p < 4; p++)
                #pragma unroll
                for (int q = 0; q < 8; q++)
                    *(ull*)&rw[(cl * 8 + q) * 64 + rg * 8 + 2 * p] = acc[p][q];
        }
        __syncthreads();

        // cell update: thread -> batch b = tid>>2, units (tid&3)*2 + {0,1}
        {
            int b = tid >> 2;
            #pragma unroll
            for (int jl = 0; jl < 2; jl++) {
                int j = (tid & 3) * 2 + jl;
                float s0 = 0.f, s1 = 0.f, s2 = 0.f, s3 = 0.f;
                #pragma unroll
                for (int ww = 0; ww < 8; ww++) {
                    const float* r = red + ww * 2048 + j * 256 + b;
                    s0 += r[0]; s1 += r[64]; s2 += r[128]; s3 += r[192];
                }
                float4 xq;
                if (DEC) xq = *(const float4*)&g_WxD[(size_t)tok[b] * 4096 + n0 + j * 4];
                else     xq = *(const float4*)&g_Xe[((size_t)t * 64 + b) * 4096 + n0 + j * 4];
                float gi = s0 + xq.x, gf = s1 + xq.y, gg = s2 + xq.z, go = s3 + xq.w;
                int ju = (n0 >> 2) + j;
                float co = g_c[b * 1024 + ju];
                float cn = sigf(gf) * co + sigf(gi) * tanhf(gg);
                g_c[b * 1024 + ju] = cn;
                h_out[b * 1024 + ju] = sigf(go) * tanhf(cn);
            }
        }
        grid_bar();
    }
}

// ---------------- phase C: logits = Hdec @ fc_W + fc_b ------------------------
__global__ void __launch_bounds__(256) phaseC_k(const float* __restrict__ fcW,
                                                const float* __restrict__ fcb,
                                                float* __restrict__ out)
{
    __shared__ __align__(16) float As[16][68];
    __shared__ __align__(16) float Bs[16][68];
    const int tid = threadIdx.x;
    const int m0 = blockIdx.x * 64;
    const int rg = tid >> 4, cg = tid & 15;
    float acc[4][4];
    #pragma unroll
    for (int p = 0; p < 4; p++)
        #pragma unroll
        for (int q = 0; q < 4; q++) acc[p][q] = 0.0f;

    for (int k0 = 0; k0 < 1024; k0 += 16) {
        { int r = tid >> 2, kq = tid & 3;
          float4 v = *(const float4*)&g_Hdec[(size_t)(m0 + r) * 1024 + k0 + kq * 4];
          As[kq * 4 + 0][r] = v.x; As[kq * 4 + 1][r] = v.y;
          As[kq * 4 + 2][r] = v.z; As[kq * 4 + 3][r] = v.w; }
        { int kk = tid >> 4, c4 = tid & 15;
          *(float4*)&Bs[kk][c4 * 4] = *(const float4*)&fcW[(size_t)(k0 + kk) * 64 + c4 * 4]; }
        __syncthreads();
        #pragma unroll
        for (int k = 0; k < 16; k++) {
            float4 a = *(const float4*)&As[k][rg * 4];
            float4 b = *(const float4*)&Bs[k][cg * 4];
            float av[4] = { a.x, a.y, a.z, a.w };
            float bv[4] = { b.x, b.y, b.z, b.w };
            #pragma unroll
            for (int p = 0; p < 4; p++)
                #pragma unroll
                for (int q = 0; q < 4; q++) acc[p][q] += av[p] * bv[q];
        }
        __syncthreads();
    }

    float4 bias = *(const float4*)&fcb[cg * 4];
    #pragma unroll
    for (int p = 0; p < 4; p++) {
        int m = m0 + rg * 4 + p;
        int b = m & 63, t = m >> 6;
        *(float4*)&out[(size_t)b * (512 * 64) + t * 64 + cg * 4] =
            make_float4(acc[p][0] + bias.x, acc[p][1] + bias.y,
                        acc[p][2] + bias.z, acc[p][3] + bias.w);
    }
}

// ---------------- launch ------------------------------------------------------
extern "C" void kernel_launch(void* const* d_in, const int* in_sizes, int n_in,
                              void* d_out, int out_size)
{
    const int*   src  = (const int*)d_in[0];
    const int*   trg  = (const int*)d_in[1];
    const float* emb  = (const float*)d_in[2];
    const float* encW = (const float*)d_in[3];
    const float* encB = (const float*)d_in[4];
    const float* decW = (const float*)d_in[5];
    const float* decB = (const float*)d_in[6];
    const float* fcW  = (const float*)d_in[7];
    const float* fcb  = (const float*)d_in[8];
    float* out = (float*)d_out;

    cudaFuncSetAttribute(persist_k<false>, cudaFuncAttributeMaxDynamicSharedMemorySize, SMEM_PERSIST);
    cudaFuncSetAttribute(persist_k<true>,  cudaFuncAttributeMaxDynamicSharedMemorySize, SMEM_PERSIST);

    prep_k<<<16384, 256>>>(encW, encB, decW, decB);
    phaseA_k<<<dim3(32, 256), 256>>>(src, emb);
    persist_k<false><<<128, 256, SMEM_PERSIST>>>((const int*)0);
    persist_k<true><<<128, 256, SMEM_PERSIST>>>(trg);
    phaseC_k<<<512, 256>>>(fcW, fcb, out);
}